// round 16
// baseline (speedup 1.0000x reference)
#include <cuda_runtime.h>
#include <cuda_fp16.h>
#include <cstdint>

// Problem constants
#define BATCH 4
#define TSEQ  2048
#define CDIM  1024
#define NHEAD 16
#define HDIM  64
#define C3    (3*CDIM)
#define MTOT  (BATCH*TSEQ)   // 8192

#define QSCALE 0.18033688011112042f   // 0.125 * log2(e)

// ---------------------------------------------------------------------------
// Device-global scratch (no allocation allowed)
// ---------------------------------------------------------------------------
__device__ __align__(256) __half g_qkv[(size_t)3 * BATCH * NHEAD * TSEQ * HDIM];
__device__ __align__(256) __half g_y[(size_t)MTOT * CDIM];
__device__ __align__(256) __half g_x[(size_t)MTOT * CDIM];
__device__ __align__(256) __half g_wq[(size_t)C3 * CDIM];     // transposed N x K
__device__ __align__(256) __half g_wp[(size_t)CDIM * CDIM];   // transposed N x K

// ---------------------------------------------------------------------------
// Helpers (baseline PTX only)
// ---------------------------------------------------------------------------
__device__ __forceinline__ uint32_t smem_u32(const void* p) {
    uint32_t a;
    asm("{ .reg .u64 t; cvta.to.shared.u64 t, %1; cvt.u32.u64 %0, t; }" : "=r"(a) : "l"(p));
    return a;
}
__device__ __forceinline__ void cpa16(uint32_t dst, const void* src) {
    asm volatile("cp.async.cg.shared.global [%0], [%1], 16;\n" :: "r"(dst), "l"(src));
}
#define CP_COMMIT() asm volatile("cp.async.commit_group;\n" ::: "memory")
#define CP_WAIT(n)  asm volatile("cp.async.wait_group %0;\n" :: "n"(n) : "memory")
#define SWZ128(o) ((o) ^ (((o) >> 3) & 0x70))

__device__ __forceinline__ void ldsm4(uint32_t addr, uint32_t* r) {
    asm volatile("ldmatrix.sync.aligned.m8n8.x4.shared.b16 {%0,%1,%2,%3}, [%4];"
                 : "=r"(r[0]), "=r"(r[1]), "=r"(r[2]), "=r"(r[3]) : "r"(addr));
}
__device__ __forceinline__ void ldsm4t(uint32_t addr, uint32_t* r) {
    asm volatile("ldmatrix.sync.aligned.m8n8.x4.trans.shared.b16 {%0,%1,%2,%3}, [%4];"
                 : "=r"(r[0]), "=r"(r[1]), "=r"(r[2]), "=r"(r[3]) : "r"(addr));
}
__device__ __forceinline__ void mma16816(float* d, const uint32_t* a, uint32_t b0, uint32_t b1) {
    asm volatile("mma.sync.aligned.m16n8k16.row.col.f32.f16.f16.f32 "
                 "{%0,%1,%2,%3},{%4,%5,%6,%7},{%8,%9},{%0,%1,%2,%3};"
                 : "+f"(d[0]), "+f"(d[1]), "+f"(d[2]), "+f"(d[3])
                 : "r"(a[0]), "r"(a[1]), "r"(a[2]), "r"(a[3]), "r"(b0), "r"(b1));
}
__device__ __forceinline__ uint32_t packh2(__half a, __half b) {
    __half2 t; t.x = a; t.y = b;
    return *reinterpret_cast<uint32_t*>(&t);
}

// ---------------------------------------------------------------------------
// Fused prep: X fp32->fp16 convert + both weight transposes, one launch.
// ---------------------------------------------------------------------------
#define N4_X     (MTOT * CDIM / 4)
#define NB_CVT   (N4_X / 256)
#define NB_WQ    ((C3 / 32) * (CDIM / 32))
#define NB_WP    ((CDIM / 32) * (CDIM / 32))
#define NB_PREP  (NB_CVT + NB_WQ + NB_WP)

__global__ void __launch_bounds__(256) prep_kernel(
    const float* __restrict__ x, const float* __restrict__ w_qkv,
    const float* __restrict__ w_proj)
{
    const int bid = blockIdx.x, tid = threadIdx.x;
    if (bid < NB_CVT) {
        int i = bid * 256 + tid;
        float4 v = ((const float4*)x)[i];
        ((uint32_t*)g_x)[2*i]   = packh2(__float2half(v.x), __float2half(v.y));
        ((uint32_t*)g_x)[2*i+1] = packh2(__float2half(v.z), __float2half(v.w));
        return;
    }
    __shared__ float t[32][33];
    const int tx = tid & 31, ty = tid >> 5;
    const float* W; __half* Th; int K, N, idx;
    if (bid < NB_CVT + NB_WQ) {
        idx = bid - NB_CVT; W = w_qkv; Th = g_wq; K = CDIM; N = C3;
    } else {
        idx = bid - NB_CVT - NB_WQ; W = w_proj; Th = g_wp; K = CDIM; N = CDIM;
    }
    const int nblk = N / 32;
    const int n0 = (idx % nblk) * 32, k0 = (idx / nblk) * 32;
    #pragma unroll
    for (int i = 0; i < 32; i += 8)
        t[ty + i][tx] = W[(size_t)(k0 + ty + i) * N + n0 + tx];
    __syncthreads();
    #pragma unroll
    for (int i = 0; i < 32; i += 8)
        Th[(size_t)(n0 + ty + i) * K + k0 + tx] = __float2half(t[tx][ty + i]);
}

// ---------------------------------------------------------------------------
// mma.sync fp16 GEMM, CTA tile 128 x NT (NT=128 or 64), BK=64 (SW128).
// MODE 0: proj -> fp32 C.   MODE 1: QKV -> head-major fp16 (Q pre-scaled).
// ---------------------------------------------------------------------------
#define ATILE_B    (128 * 128)           // 16384 B

template<int MODE, int NT>
__global__ void __launch_bounds__(256, 2) mmasync_kernel(
    const __half* __restrict__ Ah, const __half* __restrict__ Bh,
    float* __restrict__ C, int N, int K)
{
    constexpr int BTILE_B  = NT * 128;
    constexpr int STAGE_B  = ATILE_B + BTILE_B;
    constexpr int NTW      = NT / 32;
    constexpr int NP       = NT / 64;

    extern __shared__ char smraw[];
    const uint32_t smb = smem_u32(smraw);

    const int tid  = threadIdx.x;
    const int wid  = tid >> 5, lane = tid & 31;
    const int wm   = wid & 1;
    const int wn   = wid >> 1;
    const int bm   = blockIdx.y * 128, bn = blockIdx.x * NT;
    const int l16  = lane & 15, lh = lane >> 4;

    float acc[4][NTW][4];
    #pragma unroll
    for (int i = 0; i < 4; i++)
        #pragma unroll
        for (int j = 0; j < NTW; j++)
            #pragma unroll
            for (int k = 0; k < 4; k++) acc[i][j][k] = 0.f;

    auto fill = [&](int s, int k0) {
        uint32_t sb = smb + (uint32_t)s * STAGE_B;
        #pragma unroll
        for (int i = 0; i < 4; i++) {
            int chunk = tid + i * 256;
            int row = chunk >> 3, c = chunk & 7;
            cpa16(sb + SWZ128((uint32_t)(row * 128 + c * 16)),
                  Ah + (size_t)(bm + row) * K + k0 + c * 8);
        }
        #pragma unroll
        for (int i = 0; i < NT / 32; i++) {
            int chunk = tid + i * 256;
            int row = chunk >> 3, c = chunk & 7;
            cpa16(sb + ATILE_B + SWZ128((uint32_t)(row * 128 + c * 16)),
                  Bh + (size_t)(bn + row) * K + k0 + c * 8);
        }
    };

    const int nch = K >> 6;   // BK = 64
    fill(0, 0); CP_COMMIT();

    for (int i = 0; i < nch; i++) {
        if (i + 1 < nch) { fill((i + 1) & 1, (i + 1) << 6); CP_COMMIT(); CP_WAIT(1); }
        else             { CP_WAIT(0); }
        __syncthreads();

        uint32_t sb = smb + (uint32_t)(i & 1) * STAGE_B;
        uint32_t Ab = sb, Bb = sb + ATILE_B;

        #pragma unroll
        for (int kh = 0; kh < 4; kh++) {
            const uint32_t koff = (uint32_t)(kh * 32 + lh * 16);
            uint32_t ah[4][4];
            #pragma unroll
            for (int mt = 0; mt < 4; mt++) {
                uint32_t ro = SWZ128((uint32_t)((wm * 64 + mt * 16 + l16) * 128) + koff);
                ldsm4(Ab + ro, ah[mt]);
            }
            uint32_t bh[NP][4];
            #pragma unroll
            for (int np = 0; np < NP; np++) {
                uint32_t ro = SWZ128((uint32_t)((wn * (NT/4) + np * 16 + l16) * 128) + koff);
                ldsm4(Bb + ro, bh[np]);
            }
            #pragma unroll
            for (int mt = 0; mt < 4; mt++)
                #pragma unroll
                for (int nt = 0; nt < NTW; nt++) {
                    const int np = nt >> 1, o = nt & 1;
                    mma16816(acc[mt][nt], ah[mt], bh[np][o], bh[np][o + 2]);
                }
        }
        __syncthreads();
    }

    const int er = lane >> 2, ec = (lane & 3) * 2;
    #pragma unroll
    for (int mt = 0; mt < 4; mt++)
        #pragma unroll
        for (int nt = 0; nt < NTW; nt++) {
            int r0 = bm + wm * 64 + mt * 16 + er;
            int c0 = bn + wn * (NT/4) + nt * 8 + ec;
            float* v = acc[mt][nt];
            if (MODE == 0) {
                *(float2*)&C[(size_t)r0 * N + c0]       = make_float2(v[0], v[1]);
                *(float2*)&C[(size_t)(r0 + 8) * N + c0] = make_float2(v[2], v[3]);
            } else {
                int bb = r0 >> 11, t = r0 & 2047;
                int part = c0 >> 10, rem = c0 & 1023;
                int hh = rem >> 6, d = rem & 63;
                float sc = (part == 0) ? QSCALE : 1.f;
                size_t o = ((((size_t)part * BATCH + bb) * NHEAD + hh) * TSEQ + t) * HDIM + d;
                #pragma unroll
                for (int rr = 0; rr < 2; rr++) {
                    size_t oo = o + (size_t)rr * 8 * HDIM;
                    *(uint32_t*)&g_qkv[oo] = packh2(__float2half(v[2 * rr] * sc),
                                                    __float2half(v[2 * rr + 1] * sc));
                }
            }
        }
}

#define MM_SMEM_128 (2 * (ATILE_B + 128 * 128))   // 65536
#define MM_SMEM_64  (2 * (ATILE_B + 64 * 128))    // 49152

// ---------------------------------------------------------------------------
// Tensor-core flash attention (causal), fp16 1-term, Bq=128, Bk=64, D=64.
// 1D grid with global LPT; per-warp causal group-skip on diagonal blocks:
// ng = number of needed 16-key groups; interior blocks take the unrolled path.
// ---------------------------------------------------------------------------
#define FL_SMEM (64 * 1024)
#define NQT     (TSEQ / 128)   // 16

__global__ void __launch_bounds__(256, 2) flash_tc_kernel()
{
    extern __shared__ char smraw[];
    const uint32_t S = smem_u32(smraw);
    const int tid = threadIdx.x, w = tid >> 5, lane = tid & 31;
    const int l16 = lane & 15, lh = lane >> 4;
    const int bid = (int)blockIdx.x;
    const int qt = NQT - 1 - (bid >> 6);
    const int bh = bid & 63;
    const int b = bh >> 4, h = bh & 15;
    const int n_kt = 2 * qt + 2;

    const uint32_t Q_s  = S;
    const uint32_t stg0 = S + 16384;

    const size_t head = (((size_t)b) * NHEAD + h) * TSEQ * HDIM;
    const size_t HSZ  = (size_t)BATCH * NHEAD * TSEQ * HDIM;
    const __half* qp = g_qkv + head;
    const __half* kp = g_qkv + HSZ + head;
    const __half* vp = g_qkv + 2 * HSZ + head;

    {
        #pragma unroll
        for (int i = 0; i < 4; i++) {
            int idx = tid + i * 256;
            int row = idx >> 3, c = idx & 7;
            cpa16(Q_s + SWZ128((uint32_t)(row * 128 + c * 16)),
                  qp + (size_t)(qt * 128 + row) * HDIM + c * 8);
        }
    }
    auto fillkv = [&](int s, int kt) {
        uint32_t sb = stg0 + (uint32_t)s * 16384u;
        const __half* bases[2] = {kp, vp};
        #pragma unroll
        for (int i = 0; i < 4; i++) {
            int idx = tid + i * 256;
            int mtx = idx >> 9, row = (idx >> 3) & 63, c = idx & 7;
            cpa16(sb + (uint32_t)mtx * 8192u + SWZ128((uint32_t)(row * 128 + c * 16)),
                  bases[mtx] + (size_t)(kt * 64 + row) * HDIM + c * 8);
        }
    };

    fillkv(0, 0); CP_COMMIT();
    if (n_kt > 1) { fillkv(1, 1); CP_COMMIT(); }
    if (n_kt > 2) { fillkv(2, 2); CP_COMMIT(); }

    float m0 = -1e30f, m1 = -1e30f, l0 = 0.f, l1 = 0.f;
    float o[8][4];
    #pragma unroll
    for (int j = 0; j < 8; j++)
        #pragma unroll
        for (int e = 0; e < 4; e++) o[j][e] = 0.f;

    for (int kt = 0; kt < n_kt; kt++) {
        if      (kt + 2 < n_kt) { CP_WAIT(2); }
        else if (kt + 1 < n_kt) { CP_WAIT(1); }
        else                    { CP_WAIT(0); }
        __syncthreads();

        const int st = kt % 3;
        const uint32_t sb  = stg0 + (uint32_t)st * 16384u;
        const uint32_t K_s = sb, V_s = sb + 8192;

        // number of needed 16-key groups for this warp in this key block
        const int moff = qt * 128 + w * 16 + 15 - kt * 64;   // warp max row - block col0
        const int ng   = (moff >= 48) ? 4 : ((moff < 0) ? 0 : ((moff >> 4) + 1));

        float s[8][4];
        #pragma unroll
        for (int j = 0; j < 8; j++)
            #pragma unroll
            for (int e = 0; e < 4; e++) s[j][e] = 0.f;

        if (ng == 4) {
            // ---- fast path: full block (unchanged unrolled) ----
            #pragma unroll
            for (int kk = 0; kk < 4; kk++) {
                const uint32_t koff = (uint32_t)(kk * 32 + lh * 16);
                uint32_t qf[4];
                ldsm4(Q_s + SWZ128((uint32_t)((w * 16 + l16) * 128) + koff), qf);
                #pragma unroll
                for (int gp = 0; gp < 2; gp++) {
                    const int g0 = 2 * gp, g1 = 2 * gp + 1;
                    uint32_t kf0[4], kf1[4];
                    ldsm4(K_s + SWZ128((uint32_t)((g0 * 16 + l16) * 128) + koff), kf0);
                    ldsm4(K_s + SWZ128((uint32_t)((g1 * 16 + l16) * 128) + koff), kf1);
                    mma16816(s[2 * g0],     qf, kf0[0], kf0[2]);
                    mma16816(s[2 * g0 + 1], qf, kf0[1], kf0[3]);
                    mma16816(s[2 * g1],     qf, kf1[0], kf1[2]);
                    mma16816(s[2 * g1 + 1], qf, kf1[1], kf1[3]);
                }
            }
        } else {
            // ---- diagonal path: only needed groups ----
            for (int g = 0; g < ng; g++) {
                #pragma unroll
                for (int kk = 0; kk < 4; kk++) {
                    const uint32_t koff = (uint32_t)(kk * 32 + lh * 16);
                    uint32_t qf[4], kf[4];
                    ldsm4(Q_s + SWZ128((uint32_t)((w * 16 + l16) * 128) + koff), qf);
                    ldsm4(K_s + SWZ128((uint32_t)((g * 16 + l16) * 128) + koff), kf);
                    mma16816(s[2 * g],     qf, kf[0], kf[2]);
                    mma16816(s[2 * g + 1], qf, kf[1], kf[3]);
                }
            }
        }

        const int row0 = qt * 128 + w * 16 + (lane >> 2);
        if (kt * 64 + 63 > qt * 128 + w * 16) {
            #pragma unroll
            for (int j = 0; j < 8; j++) {
                int colb = kt * 64 + j * 8 + (lane & 3) * 2;
                if (colb + 0 > row0)     s[j][0] = -1e30f;
                if (colb + 1 > row0)     s[j][1] = -1e30f;
                if (colb + 0 > row0 + 8) s[j][2] = -1e30f;
                if (colb + 1 > row0 + 8) s[j][3] = -1e30f;
            }
        }

        float mx0 = -1e30f, mx1 = -1e30f;
        #pragma unroll
        for (int j = 0; j < 8; j++) {
            mx0 = fmaxf(mx0, fmaxf(s[j][0], s[j][1]));
            mx1 = fmaxf(mx1, fmaxf(s[j][2], s[j][3]));
        }
        mx0 = fmaxf(mx0, __shfl_xor_sync(0xffffffffu, mx0, 1));
        mx0 = fmaxf(mx0, __shfl_xor_sync(0xffffffffu, mx0, 2));
        mx1 = fmaxf(mx1, __shfl_xor_sync(0xffffffffu, mx1, 1));
        mx1 = fmaxf(mx1, __shfl_xor_sync(0xffffffffu, mx1, 2));
        float nm0 = fmaxf(m0, mx0), nm1 = fmaxf(m1, mx1);
        float c0 = exp2f(m0 - nm0), c1 = exp2f(m1 - nm1);
        m0 = nm0; m1 = nm1;
        float sum0 = 0.f, sum1 = 0.f;
        #pragma unroll
        for (int j = 0; j < 8; j++) {
            s[j][0] = exp2f(s[j][0] - m0);
            s[j][1] = exp2f(s[j][1] - m0);
            s[j][2] = exp2f(s[j][2] - m1);
            s[j][3] = exp2f(s[j][3] - m1);
            sum0 += s[j][0] + s[j][1];
            sum1 += s[j][2] + s[j][3];
        }
        sum0 += __shfl_xor_sync(0xffffffffu, sum0, 1);
        sum0 += __shfl_xor_sync(0xffffffffu, sum0, 2);
        sum1 += __shfl_xor_sync(0xffffffffu, sum1, 1);
        sum1 += __shfl_xor_sync(0xffffffffu, sum1, 2);
        l0 = l0 * c0 + sum0;
        l1 = l1 * c1 + sum1;
        #pragma unroll
        for (int j = 0; j < 8; j++) {
            o[j][0] *= c0; o[j][1] *= c0; o[j][2] *= c1; o[j][3] *= c1;
        }

        // ---- O += P V : contraction over key groups kk < ng (P=0 beyond) ----
        if (ng == 4) {
            #pragma unroll
            for (int kk = 0; kk < 4; kk++) {
                uint32_t pa[4];
                #pragma unroll
                for (int half = 0; half < 2; half++) {
                    const int f = 2 * kk + half;
                    pa[2 * half + 0] = packh2(__float2half(s[f][0]), __float2half(s[f][1]));
                    pa[2 * half + 1] = packh2(__float2half(s[f][2]), __float2half(s[f][3]));
                }
                #pragma unroll
                for (int gp = 0; gp < 2; gp++) {
                    const int g0 = 2 * gp, g1 = 2 * gp + 1;
                    uint32_t vf0[4], vf1[4];
                    uint32_t ro0 = SWZ128((uint32_t)((kk * 16 + l16) * 128 + g0 * 32) + (uint32_t)(lh * 16));
                    uint32_t ro1 = SWZ128((uint32_t)((kk * 16 + l16) * 128 + g1 * 32) + (uint32_t)(lh * 16));
                    ldsm4t(V_s + ro0, vf0);
                    ldsm4t(V_s + ro1, vf1);
                    mma16816(o[2 * g0],     pa, vf0[0], vf0[1]);
                    mma16816(o[2 * g0 + 1], pa, vf0[2], vf0[3]);
                    mma16816(o[2 * g1],     pa, vf1[0], vf1[1]);
                    mma16816(o[2 * g1 + 1], pa, vf1[2], vf1[3]);
                }
            }
        } else {
            for (int kk = 0; kk < ng; kk++) {
                uint32_t pa[4];
                #pragma unroll
                for (int half = 0; half < 2; half++) {
                    const int f = 2 * kk + half;
                    pa[2 * half + 0] = packh2(__float2half(s[f][0]), __float2half(s[f][1]));
                    pa[2 * half + 1] = packh2(__float2half(s[f][2]), __float2half(s[f][3]));
                }
                #pragma unroll
                for (int gp = 0; gp < 2; gp++) {
                    const int g0 = 2 * gp, g1 = 2 * gp + 1;
                    uint32_t vf0[4], vf1[4];
                    uint32_t ro0 = SWZ128((uint32_t)((kk * 16 + l16) * 128 + g0 * 32) + (uint32_t)(lh * 16));
                    uint32_t ro1 = SWZ128((uint32_t)((kk * 16 + l16) * 128 + g1 * 32) + (uint32_t)(lh * 16));
                    ldsm4t(V_s + ro0, vf0);
                    ldsm4t(V_s + ro1, vf1);
                    mma16816(o[2 * g0],     pa, vf0[0], vf0[1]);
                    mma16816(o[2 * g0 + 1], pa, vf0[2], vf0[3]);
                    mma16816(o[2 * g1],     pa, vf1[0], vf1[1]);
                    mma16816(o[2 * g1 + 1], pa, vf1[2], vf1[3]);
                }
            }
        }

        __syncthreads();
        if (kt + 3 < n_kt) { fillkv(st, kt + 3); CP_COMMIT(); }
    }

    const float inv0 = 1.f / l0, inv1 = 1.f / l1;
    const int r0 = qt * 128 + w * 16 + (lane >> 2);
    const int t0 = r0, t1 = r0 + 8;
    #pragma unroll
    for (int j = 0; j < 8; j++) {
        int d = j * 8 + (lane & 3) * 2;
        size_t o0 = ((size_t)b * TSEQ + t0) * CDIM + h * HDIM + d;
        size_t o1 = ((size_t)b * TSEQ + t1) * CDIM + h * HDIM + d;
        *(uint32_t*)&g_y[o0] = packh2(__float2half(o[j][0] * inv0),
                                      __float2half(o[j][1] * inv0));
        *(uint32_t*)&g_y[o1] = packh2(__float2half(o[j][2] * inv1),
                                      __float2half(o[j][3] * inv1));
    }
}

// ---------------------------------------------------------------------------
extern "C" void kernel_launch(void* const* d_in, const int* in_sizes, int n_in,
                              void* d_out, int out_size)
{
    const float* x      = (const float*)d_in[0];
    const float* w_qkv  = (const float*)d_in[1];
    const float* w_proj = (const float*)d_in[2];
    float* out = (float*)d_out;

    __half *xh, *yh, *wq, *wp;
    cudaGetSymbolAddress((void**)&xh, g_x);
    cudaGetSymbolAddress((void**)&yh, g_y);
    cudaGetSymbolAddress((void**)&wq, g_wq);
    cudaGetSymbolAddress((void**)&wp, g_wp);

    cudaFuncSetAttribute((const void*)mmasync_kernel<1,128>, cudaFuncAttributeMaxDynamicSharedMemorySize, MM_SMEM_128);
    cudaFuncSetAttribute((const void*)mmasync_kernel<0,64>,  cudaFuncAttributeMaxDynamicSharedMemorySize, MM_SMEM_64);
    cudaFuncSetAttribute((const void*)flash_tc_kernel,       cudaFuncAttributeMaxDynamicSharedMemorySize, FL_SMEM);
    cudaFuncSetAttribute((const void*)mmasync_kernel<1,128>, cudaFuncAttributePreferredSharedMemoryCarveout, 100);
    cudaFuncSetAttribute((const void*)mmasync_kernel<0,64>,  cudaFuncAttributePreferredSharedMemoryCarveout, 100);
    cudaFuncSetAttribute((const void*)flash_tc_kernel,       cudaFuncAttributePreferredSharedMemoryCarveout, 100);

    // 1) fused prep
    prep_kernel<<<NB_PREP, 256>>>(x, w_qkv, w_proj);

    // 2) QKV GEMM (N=3072, 128-wide tiles)
    {
        dim3 grid(C3 / 128, MTOT / 128);
        mmasync_kernel<1,128><<<grid, 256, MM_SMEM_128>>>(xh, wq, nullptr, C3, CDIM);
    }

    // 3) flash attention, 1D LPT grid
    flash_tc_kernel<<<NQT * NHEAD * BATCH, 256, FL_SMEM>>>();

    // 4) proj GEMM (64-wide tiles)
    {
        dim3 grid(CDIM / 64, MTOT / 128);
        mmasync_kernel<0,64><<<grid, 256, MM_SMEM_64>>>(yh, wp, out, CDIM, CDIM);
    }
    (void)in_sizes; (void)n_in; (void)out_size;
}

// round 17
// speedup vs baseline: 1.4442x; 1.4442x over previous
#include <cuda_runtime.h>
#include <cuda_fp16.h>
#include <cstdint>

// Problem constants
#define BATCH 4
#define TSEQ  2048
#define CDIM  1024
#define NHEAD 16
#define HDIM  64
#define C3    (3*CDIM)
#define MTOT  (BATCH*TSEQ)   // 8192

#define QSCALE 0.18033688011112042f   // 0.125 * log2(e)

// ---------------------------------------------------------------------------
// Device-global scratch (no allocation allowed)
// ---------------------------------------------------------------------------
__device__ __align__(256) __half g_qkv[(size_t)3 * BATCH * NHEAD * TSEQ * HDIM];
__device__ __align__(256) __half g_y[(size_t)MTOT * CDIM];
__device__ __align__(256) __half g_x[(size_t)MTOT * CDIM];
__device__ __align__(256) __half g_wq[(size_t)C3 * CDIM];     // transposed N x K
__device__ __align__(256) __half g_wp[(size_t)CDIM * CDIM];   // transposed N x K

// ---------------------------------------------------------------------------
// Helpers (baseline PTX only)
// ---------------------------------------------------------------------------
__device__ __forceinline__ uint32_t smem_u32(const void* p) {
    uint32_t a;
    asm("{ .reg .u64 t; cvta.to.shared.u64 t, %1; cvt.u32.u64 %0, t; }" : "=r"(a) : "l"(p));
    return a;
}
__device__ __forceinline__ void cpa16(uint32_t dst, const void* src) {
    asm volatile("cp.async.cg.shared.global [%0], [%1], 16;\n" :: "r"(dst), "l"(src));
}
#define CP_COMMIT() asm volatile("cp.async.commit_group;\n" ::: "memory")
#define CP_WAIT(n)  asm volatile("cp.async.wait_group %0;\n" :: "n"(n) : "memory")
#define SWZ128(o) ((o) ^ (((o) >> 3) & 0x70))

__device__ __forceinline__ void ldsm4(uint32_t addr, uint32_t* r) {
    asm volatile("ldmatrix.sync.aligned.m8n8.x4.shared.b16 {%0,%1,%2,%3}, [%4];"
                 : "=r"(r[0]), "=r"(r[1]), "=r"(r[2]), "=r"(r[3]) : "r"(addr));
}
__device__ __forceinline__ void ldsm4t(uint32_t addr, uint32_t* r) {
    asm volatile("ldmatrix.sync.aligned.m8n8.x4.trans.shared.b16 {%0,%1,%2,%3}, [%4];"
                 : "=r"(r[0]), "=r"(r[1]), "=r"(r[2]), "=r"(r[3]) : "r"(addr));
}
__device__ __forceinline__ void mma16816(float* d, const uint32_t* a, uint32_t b0, uint32_t b1) {
    asm volatile("mma.sync.aligned.m16n8k16.row.col.f32.f16.f16.f32 "
                 "{%0,%1,%2,%3},{%4,%5,%6,%7},{%8,%9},{%0,%1,%2,%3};"
                 : "+f"(d[0]), "+f"(d[1]), "+f"(d[2]), "+f"(d[3])
                 : "r"(a[0]), "r"(a[1]), "r"(a[2]), "r"(a[3]), "r"(b0), "r"(b1));
}
__device__ __forceinline__ uint32_t packh2(__half a, __half b) {
    __half2 t; t.x = a; t.y = b;
    return *reinterpret_cast<uint32_t*>(&t);
}

// ---------------------------------------------------------------------------
// Fused prep: X fp32->fp16 convert + both weight transposes, one launch.
// ---------------------------------------------------------------------------
#define N4_X     (MTOT * CDIM / 4)
#define NB_CVT   (N4_X / 256)
#define NB_WQ    ((C3 / 32) * (CDIM / 32))
#define NB_WP    ((CDIM / 32) * (CDIM / 32))
#define NB_PREP  (NB_CVT + NB_WQ + NB_WP)

__global__ void __launch_bounds__(256) prep_kernel(
    const float* __restrict__ x, const float* __restrict__ w_qkv,
    const float* __restrict__ w_proj)
{
    const int bid = blockIdx.x, tid = threadIdx.x;
    if (bid < NB_CVT) {
        int i = bid * 256 + tid;
        float4 v = ((const float4*)x)[i];
        ((uint32_t*)g_x)[2*i]   = packh2(__float2half(v.x), __float2half(v.y));
        ((uint32_t*)g_x)[2*i+1] = packh2(__float2half(v.z), __float2half(v.w));
        return;
    }
    __shared__ float t[32][33];
    const int tx = tid & 31, ty = tid >> 5;
    const float* W; __half* Th; int K, N, idx;
    if (bid < NB_CVT + NB_WQ) {
        idx = bid - NB_CVT; W = w_qkv; Th = g_wq; K = CDIM; N = C3;
    } else {
        idx = bid - NB_CVT - NB_WQ; W = w_proj; Th = g_wp; K = CDIM; N = CDIM;
    }
    const int nblk = N / 32;
    const int n0 = (idx % nblk) * 32, k0 = (idx / nblk) * 32;
    #pragma unroll
    for (int i = 0; i < 32; i += 8)
        t[ty + i][tx] = W[(size_t)(k0 + ty + i) * N + n0 + tx];
    __syncthreads();
    #pragma unroll
    for (int i = 0; i < 32; i += 8)
        Th[(size_t)(n0 + ty + i) * K + k0 + tx] = __float2half(t[tx][ty + i]);
}

// ---------------------------------------------------------------------------
// mma.sync fp16 GEMM, CTA tile 128 x NT (NT=128 or 64), BK=64 (SW128).
// MODE 0: proj -> fp32 C.   MODE 1: QKV -> head-major fp16 (Q pre-scaled).
// ---------------------------------------------------------------------------
#define ATILE_B    (128 * 128)           // 16384 B

template<int MODE, int NT>
__global__ void __launch_bounds__(256, 2) mmasync_kernel(
    const __half* __restrict__ Ah, const __half* __restrict__ Bh,
    float* __restrict__ C, int N, int K)
{
    constexpr int BTILE_B  = NT * 128;
    constexpr int STAGE_B  = ATILE_B + BTILE_B;
    constexpr int NTW      = NT / 32;
    constexpr int NP       = NT / 64;

    extern __shared__ char smraw[];
    const uint32_t smb = smem_u32(smraw);

    const int tid  = threadIdx.x;
    const int wid  = tid >> 5, lane = tid & 31;
    const int wm   = wid & 1;
    const int wn   = wid >> 1;
    const int bm   = blockIdx.y * 128, bn = blockIdx.x * NT;
    const int l16  = lane & 15, lh = lane >> 4;

    float acc[4][NTW][4];
    #pragma unroll
    for (int i = 0; i < 4; i++)
        #pragma unroll
        for (int j = 0; j < NTW; j++)
            #pragma unroll
            for (int k = 0; k < 4; k++) acc[i][j][k] = 0.f;

    auto fill = [&](int s, int k0) {
        uint32_t sb = smb + (uint32_t)s * STAGE_B;
        #pragma unroll
        for (int i = 0; i < 4; i++) {
            int chunk = tid + i * 256;
            int row = chunk >> 3, c = chunk & 7;
            cpa16(sb + SWZ128((uint32_t)(row * 128 + c * 16)),
                  Ah + (size_t)(bm + row) * K + k0 + c * 8);
        }
        #pragma unroll
        for (int i = 0; i < NT / 32; i++) {
            int chunk = tid + i * 256;
            int row = chunk >> 3, c = chunk & 7;
            cpa16(sb + ATILE_B + SWZ128((uint32_t)(row * 128 + c * 16)),
                  Bh + (size_t)(bn + row) * K + k0 + c * 8);
        }
    };

    const int nch = K >> 6;   // BK = 64
    fill(0, 0); CP_COMMIT();

    for (int i = 0; i < nch; i++) {
        if (i + 1 < nch) { fill((i + 1) & 1, (i + 1) << 6); CP_COMMIT(); CP_WAIT(1); }
        else             { CP_WAIT(0); }
        __syncthreads();

        uint32_t sb = smb + (uint32_t)(i & 1) * STAGE_B;
        uint32_t Ab = sb, Bb = sb + ATILE_B;

        #pragma unroll
        for (int kh = 0; kh < 4; kh++) {
            const uint32_t koff = (uint32_t)(kh * 32 + lh * 16);
            uint32_t ah[4][4];
            #pragma unroll
            for (int mt = 0; mt < 4; mt++) {
                uint32_t ro = SWZ128((uint32_t)((wm * 64 + mt * 16 + l16) * 128) + koff);
                ldsm4(Ab + ro, ah[mt]);
            }
            uint32_t bh[NP][4];
            #pragma unroll
            for (int np = 0; np < NP; np++) {
                uint32_t ro = SWZ128((uint32_t)((wn * (NT/4) + np * 16 + l16) * 128) + koff);
                ldsm4(Bb + ro, bh[np]);
            }
            #pragma unroll
            for (int mt = 0; mt < 4; mt++)
                #pragma unroll
                for (int nt = 0; nt < NTW; nt++) {
                    const int np = nt >> 1, o = nt & 1;
                    mma16816(acc[mt][nt], ah[mt], bh[np][o], bh[np][o + 2]);
                }
        }
        __syncthreads();
    }

    const int er = lane >> 2, ec = (lane & 3) * 2;
    #pragma unroll
    for (int mt = 0; mt < 4; mt++)
        #pragma unroll
        for (int nt = 0; nt < NTW; nt++) {
            int r0 = bm + wm * 64 + mt * 16 + er;
            int c0 = bn + wn * (NT/4) + nt * 8 + ec;
            float* v = acc[mt][nt];
            if (MODE == 0) {
                *(float2*)&C[(size_t)r0 * N + c0]       = make_float2(v[0], v[1]);
                *(float2*)&C[(size_t)(r0 + 8) * N + c0] = make_float2(v[2], v[3]);
            } else {
                int bb = r0 >> 11, t = r0 & 2047;
                int part = c0 >> 10, rem = c0 & 1023;
                int hh = rem >> 6, d = rem & 63;
                float sc = (part == 0) ? QSCALE : 1.f;
                size_t o = ((((size_t)part * BATCH + bb) * NHEAD + hh) * TSEQ + t) * HDIM + d;
                #pragma unroll
                for (int rr = 0; rr < 2; rr++) {
                    size_t oo = o + (size_t)rr * 8 * HDIM;
                    *(uint32_t*)&g_qkv[oo] = packh2(__float2half(v[2 * rr] * sc),
                                                    __float2half(v[2 * rr + 1] * sc));
                }
            }
        }
}

#define MM_SMEM_128 (2 * (ATILE_B + 128 * 128))   // 65536
#define MM_SMEM_64  (2 * (ATILE_B + 64 * 128))    // 49152

// ---------------------------------------------------------------------------
// Tensor-core flash attention (causal), fp16 1-term, Bq=128, Bk=64, D=64.
// 1D grid with global LPT; STATIC final-block warp-skip only (no dynamic
// register-array indexing — R16 lesson).
// ---------------------------------------------------------------------------
#define FL_SMEM (64 * 1024)
#define NQT     (TSEQ / 128)   // 16

__global__ void __launch_bounds__(256, 2) flash_tc_kernel()
{
    extern __shared__ char smraw[];
    const uint32_t S = smem_u32(smraw);
    const int tid = threadIdx.x, w = tid >> 5, lane = tid & 31;
    const int l16 = lane & 15, lh = lane >> 4;
    const int bid = (int)blockIdx.x;
    const int qt = NQT - 1 - (bid >> 6);     // global heaviest-first (LPT)
    const int bh = bid & 63;
    const int b = bh >> 4, h = bh & 15;
    const int n_kt = 2 * qt + 2;

    const uint32_t Q_s  = S;
    const uint32_t stg0 = S + 16384;

    const size_t head = (((size_t)b) * NHEAD + h) * TSEQ * HDIM;
    const size_t HSZ  = (size_t)BATCH * NHEAD * TSEQ * HDIM;
    const __half* qp = g_qkv + head;
    const __half* kp = g_qkv + HSZ + head;
    const __half* vp = g_qkv + 2 * HSZ + head;

    {
        #pragma unroll
        for (int i = 0; i < 4; i++) {
            int idx = tid + i * 256;
            int row = idx >> 3, c = idx & 7;
            cpa16(Q_s + SWZ128((uint32_t)(row * 128 + c * 16)),
                  qp + (size_t)(qt * 128 + row) * HDIM + c * 8);
        }
    }
    auto fillkv = [&](int s, int kt) {
        uint32_t sb = stg0 + (uint32_t)s * 16384u;
        const __half* bases[2] = {kp, vp};
        #pragma unroll
        for (int i = 0; i < 4; i++) {
            int idx = tid + i * 256;
            int mtx = idx >> 9, row = (idx >> 3) & 63, c = idx & 7;
            cpa16(sb + (uint32_t)mtx * 8192u + SWZ128((uint32_t)(row * 128 + c * 16)),
                  bases[mtx] + (size_t)(kt * 64 + row) * HDIM + c * 8);
        }
    };

    fillkv(0, 0); CP_COMMIT();
    if (n_kt > 1) { fillkv(1, 1); CP_COMMIT(); }
    if (n_kt > 2) { fillkv(2, 2); CP_COMMIT(); }

    float m0 = -1e30f, m1 = -1e30f, l0 = 0.f, l1 = 0.f;
    float o[8][4];
    #pragma unroll
    for (int j = 0; j < 8; j++)
        #pragma unroll
        for (int e = 0; e < 4; e++) o[j][e] = 0.f;

    for (int kt = 0; kt < n_kt; kt++) {
        if      (kt + 2 < n_kt) { CP_WAIT(2); }
        else if (kt + 1 < n_kt) { CP_WAIT(1); }
        else                    { CP_WAIT(0); }
        __syncthreads();

        const bool skip = (kt == n_kt - 1) && (w < 4);
        const int st = kt % 3;
        const uint32_t sb  = stg0 + (uint32_t)st * 16384u;
        const uint32_t K_s = sb, V_s = sb + 8192;

        if (!skip) {
            float s[8][4];
            #pragma unroll
            for (int j = 0; j < 8; j++)
                #pragma unroll
                for (int e = 0; e < 4; e++) s[j][e] = 0.f;

            #pragma unroll
            for (int kk = 0; kk < 4; kk++) {
                const uint32_t koff = (uint32_t)(kk * 32 + lh * 16);
                uint32_t qf[4];
                ldsm4(Q_s + SWZ128((uint32_t)((w * 16 + l16) * 128) + koff), qf);
                #pragma unroll
                for (int gp = 0; gp < 2; gp++) {
                    const int g0 = 2 * gp, g1 = 2 * gp + 1;
                    uint32_t kf0[4], kf1[4];
                    ldsm4(K_s + SWZ128((uint32_t)((g0 * 16 + l16) * 128) + koff), kf0);
                    ldsm4(K_s + SWZ128((uint32_t)((g1 * 16 + l16) * 128) + koff), kf1);
                    mma16816(s[2 * g0],     qf, kf0[0], kf0[2]);
                    mma16816(s[2 * g0 + 1], qf, kf0[1], kf0[3]);
                    mma16816(s[2 * g1],     qf, kf1[0], kf1[2]);
                    mma16816(s[2 * g1 + 1], qf, kf1[1], kf1[3]);
                }
            }

            const int row0 = qt * 128 + w * 16 + (lane >> 2);
            if (kt * 64 + 63 > qt * 128 + w * 16) {
                #pragma unroll
                for (int j = 0; j < 8; j++) {
                    int colb = kt * 64 + j * 8 + (lane & 3) * 2;
                    if (colb + 0 > row0)     s[j][0] = -1e30f;
                    if (colb + 1 > row0)     s[j][1] = -1e30f;
                    if (colb + 0 > row0 + 8) s[j][2] = -1e30f;
                    if (colb + 1 > row0 + 8) s[j][3] = -1e30f;
                }
            }

            float mx0 = -1e30f, mx1 = -1e30f;
            #pragma unroll
            for (int j = 0; j < 8; j++) {
                mx0 = fmaxf(mx0, fmaxf(s[j][0], s[j][1]));
                mx1 = fmaxf(mx1, fmaxf(s[j][2], s[j][3]));
            }
            mx0 = fmaxf(mx0, __shfl_xor_sync(0xffffffffu, mx0, 1));
            mx0 = fmaxf(mx0, __shfl_xor_sync(0xffffffffu, mx0, 2));
            mx1 = fmaxf(mx1, __shfl_xor_sync(0xffffffffu, mx1, 1));
            mx1 = fmaxf(mx1, __shfl_xor_sync(0xffffffffu, mx1, 2));
            float nm0 = fmaxf(m0, mx0), nm1 = fmaxf(m1, mx1);
            float c0 = exp2f(m0 - nm0), c1 = exp2f(m1 - nm1);
            m0 = nm0; m1 = nm1;
            float sum0 = 0.f, sum1 = 0.f;
            #pragma unroll
            for (int j = 0; j < 8; j++) {
                s[j][0] = exp2f(s[j][0] - m0);
                s[j][1] = exp2f(s[j][1] - m0);
                s[j][2] = exp2f(s[j][2] - m1);
                s[j][3] = exp2f(s[j][3] - m1);
                sum0 += s[j][0] + s[j][1];
                sum1 += s[j][2] + s[j][3];
            }
            sum0 += __shfl_xor_sync(0xffffffffu, sum0, 1);
            sum0 += __shfl_xor_sync(0xffffffffu, sum0, 2);
            sum1 += __shfl_xor_sync(0xffffffffu, sum1, 1);
            sum1 += __shfl_xor_sync(0xffffffffu, sum1, 2);
            l0 = l0 * c0 + sum0;
            l1 = l1 * c1 + sum1;
            #pragma unroll
            for (int j = 0; j < 8; j++) {
                o[j][0] *= c0; o[j][1] *= c0; o[j][2] *= c1; o[j][3] *= c1;
            }

            #pragma unroll
            for (int kk = 0; kk < 4; kk++) {
                uint32_t pa[4];
                #pragma unroll
                for (int half = 0; half < 2; half++) {
                    const int f = 2 * kk + half;
                    pa[2 * half + 0] = packh2(__float2half(s[f][0]), __float2half(s[f][1]));
                    pa[2 * half + 1] = packh2(__float2half(s[f][2]), __float2half(s[f][3]));
                }
                #pragma unroll
                for (int gp = 0; gp < 2; gp++) {
                    const int g0 = 2 * gp, g1 = 2 * gp + 1;
                    uint32_t vf0[4], vf1[4];
                    uint32_t ro0 = SWZ128((uint32_t)((kk * 16 + l16) * 128 + g0 * 32) + (uint32_t)(lh * 16));
                    uint32_t ro1 = SWZ128((uint32_t)((kk * 16 + l16) * 128 + g1 * 32) + (uint32_t)(lh * 16));
                    ldsm4t(V_s + ro0, vf0);
                    ldsm4t(V_s + ro1, vf1);
                    mma16816(o[2 * g0],     pa, vf0[0], vf0[1]);
                    mma16816(o[2 * g0 + 1], pa, vf0[2], vf0[3]);
                    mma16816(o[2 * g1],     pa, vf1[0], vf1[1]);
                    mma16816(o[2 * g1 + 1], pa, vf1[2], vf1[3]);
                }
            }
        }

        __syncthreads();
        if (kt + 3 < n_kt) { fillkv(st, kt + 3); CP_COMMIT(); }
    }

    const float inv0 = 1.f / l0, inv1 = 1.f / l1;
    const int r0 = qt * 128 + w * 16 + (lane >> 2);
    const int t0 = r0, t1 = r0 + 8;
    #pragma unroll
    for (int j = 0; j < 8; j++) {
        int d = j * 8 + (lane & 3) * 2;
        size_t o0 = ((size_t)b * TSEQ + t0) * CDIM + h * HDIM + d;
        size_t o1 = ((size_t)b * TSEQ + t1) * CDIM + h * HDIM + d;
        *(uint32_t*)&g_y[o0] = packh2(__float2half(o[j][0] * inv0),
                                      __float2half(o[j][1] * inv0));
        *(uint32_t*)&g_y[o1] = packh2(__float2half(o[j][2] * inv1),
                                      __float2half(o[j][3] * inv1));
    }
}

// ---------------------------------------------------------------------------
extern "C" void kernel_launch(void* const* d_in, const int* in_sizes, int n_in,
                              void* d_out, int out_size)
{
    const float* x      = (const float*)d_in[0];
    const float* w_qkv  = (const float*)d_in[1];
    const float* w_proj = (const float*)d_in[2];
    float* out = (float*)d_out;

    __half *xh, *yh, *wq, *wp;
    cudaGetSymbolAddress((void**)&xh, g_x);
    cudaGetSymbolAddress((void**)&yh, g_y);
    cudaGetSymbolAddress((void**)&wq, g_wq);
    cudaGetSymbolAddress((void**)&wp, g_wp);

    cudaFuncSetAttribute((const void*)mmasync_kernel<1,128>, cudaFuncAttributeMaxDynamicSharedMemorySize, MM_SMEM_128);
    cudaFuncSetAttribute((const void*)mmasync_kernel<0,64>,  cudaFuncAttributeMaxDynamicSharedMemorySize, MM_SMEM_64);
    cudaFuncSetAttribute((const void*)flash_tc_kernel,       cudaFuncAttributeMaxDynamicSharedMemorySize, FL_SMEM);
    cudaFuncSetAttribute((const void*)mmasync_kernel<1,128>, cudaFuncAttributePreferredSharedMemoryCarveout, 100);
    cudaFuncSetAttribute((const void*)mmasync_kernel<0,64>,  cudaFuncAttributePreferredSharedMemoryCarveout, 100);
    cudaFuncSetAttribute((const void*)flash_tc_kernel,       cudaFuncAttributePreferredSharedMemoryCarveout, 100);

    // 1) fused prep
    prep_kernel<<<NB_PREP, 256>>>(x, w_qkv, w_proj);

    // 2) QKV GEMM (N=3072, 128-wide tiles)
    {
        dim3 grid(C3 / 128, MTOT / 128);
        mmasync_kernel<1,128><<<grid, 256, MM_SMEM_128>>>(xh, wq, nullptr, C3, CDIM);
    }

    // 3) flash attention, 1D LPT grid
    flash_tc_kernel<<<NQT * NHEAD * BATCH, 256, FL_SMEM>>>();

    // 4) proj GEMM (64-wide tiles)
    {
        dim3 grid(CDIM / 64, MTOT / 128);
        mmasync_kernel<0,64><<<grid, 256, MM_SMEM_64>>>(yh, wp, out, CDIM, CDIM);
    }
    (void)in_sizes; (void)n_in; (void)out_size;
}